// round 1
// baseline (speedup 1.0000x reference)
#include <cuda_runtime.h>
#include <math.h>

// Fixed problem shapes (from reference setup_inputs)
#define B_  4
#define C_  64
#define H_  192
#define W_  192
#define OH_ 384
#define OW_ 384
#define E_  4
#define R_  4
#define HID_ 64

// 4 parity variants: rw[0..3], offx, offy
__device__ float g_var[4][6];

__device__ __forceinline__ float gelu_exact(float x) {
    return 0.5f * x * (1.0f + erff(x * 0.7071067811865476f));
}

// ---------------------------------------------------------------------------
// Kernel A: evaluate the per-pixel MLP at the 4 distinct coordinate-feature
// values (oy parity × ox parity). 1 block, 256 threads = 4 variants × 64 j.
// ---------------------------------------------------------------------------
__global__ void mlp4_kernel(const float* __restrict__ w1, const float* __restrict__ b1,
                            const float* __restrict__ w2, const float* __restrict__ b2,
                            const float* __restrict__ rww, const float* __restrict__ rwb,
                            const float* __restrict__ ofw, const float* __restrict__ ofb) {
    __shared__ float emb1[4][64];
    __shared__ float emb2[4][64];
    int t = threadIdx.x;
    int v = t >> 6;       // variant 0..3  (bit1 = oy parity, bit0 = ox parity)
    int j = t & 63;

    const float sh = (float)OH_ / (float)H_;   // 2.0
    const float sw = (float)OW_ / (float)W_;   // 2.0
    int py = v >> 1, px = v & 1;
    float chv = ((float)py + 0.5f) / sh;
    float coor_h = chv - floorf(chv + 1e-6f) - 0.5f;
    float cwv = ((float)px + 0.5f) / sw;
    float coor_w = cwv - floorf(cwv + 1e-6f) - 0.5f;
    // feat order: [1/scale_w, 1/scale_h, coor_h, coor_w]
    float f0 = 1.0f / sw, f1 = 1.0f / sh, f2 = coor_h, f3 = coor_w;

    float a = b1[j];
    a = fmaf(f0, w1[j * 4 + 0], a);
    a = fmaf(f1, w1[j * 4 + 1], a);
    a = fmaf(f2, w1[j * 4 + 2], a);
    a = fmaf(f3, w1[j * 4 + 3], a);
    emb1[v][j] = gelu_exact(a);
    __syncthreads();

    float acc = b2[j];
    #pragma unroll 16
    for (int i = 0; i < 64; i++) acc = fmaf(emb1[v][i], w2[j * 64 + i], acc);
    emb2[v][j] = gelu_exact(acc);
    __syncthreads();

    if (t < 4) {
        int vv = t;
        #pragma unroll
        for (int e = 0; e < E_; e++) {
            float s = rwb[e];
            for (int i = 0; i < 64; i++) s = fmaf(emb2[vv][i], rww[e * 64 + i], s);
            g_var[vv][e] = 1.0f / (1.0f + expf(-s));
        }
        #pragma unroll
        for (int d = 0; d < 2; d++) {
            float s = ofb[d];
            for (int i = 0; i < 64; i++) s = fmaf(emb2[vv][i], ofw[d * 64 + i], s);
            g_var[vv][4 + d] = s;
        }
    }
}

// ---------------------------------------------------------------------------
// Kernel B: fused bilinear gather + per-pixel dynamic MoE compress/expand.
// grid = (1152, 4)  [3 x-chunks * 384 rows, batch], block = 128 threads.
// Thread = one output pixel of one batch. fea0[64] stays in registers.
// ---------------------------------------------------------------------------
__global__ void __launch_bounds__(128)
upsample_kernel(const float* __restrict__ x, const float* __restrict__ wc_g,
                const float* __restrict__ we_g, float* __restrict__ out) {
    // Wc_s[c][e*4+r] = weight_compress[e][r][c];  We_s[c][e*4+r] = weight_expand[e][c][r]
    __shared__ float4 Wc4[64][4];
    __shared__ float4 We4[64][4];
    __shared__ float var_s[4][6];

    int tid = threadIdx.x;
    for (int i = tid; i < 1024; i += 128) {
        int c = i >> 4, j = i & 15;
        int e = j >> 2, r = j & 3;
        ((float*)Wc4)[c * 16 + j] = wc_g[e * 256 + r * 64 + c];
        ((float*)We4)[c * 16 + j] = we_g[e * 256 + c * 4 + r];
    }
    if (tid < 24) ((float*)var_s)[tid] = ((const float*)g_var)[tid];
    __syncthreads();

    int b  = blockIdx.y;
    int bx = blockIdx.x;
    int oy = bx / 3;
    int ox = (bx - oy * 3) * 128 + tid;

    int v = ((oy & 1) << 1) | (ox & 1);
    float rw0 = var_s[v][0], rw1 = var_s[v][1], rw2 = var_s[v][2], rw3 = var_s[v][3];
    float offx = var_s[v][4], offy = var_s[v][5];

    // grid_sample coordinates (align_corners=False, zero padding) + learned offset
    const float sw = 2.0f, sh = 2.0f;
    const float inv_wm1 = 2.0f / (float)(W_ - 1);
    const float inv_hm1 = 2.0f / (float)(H_ - 1);
    float gx = (((float)ox + 0.5f) / sw - 0.5f) * inv_wm1 - 1.0f + offx * inv_wm1;
    float gy = (((float)oy + 0.5f) / sh - 0.5f) * inv_hm1 - 1.0f + offy * inv_hm1;
    float ixf = (gx + 1.0f) * ((float)W_ * 0.5f) - 0.5f;
    float iyf = (gy + 1.0f) * ((float)H_ * 0.5f) - 0.5f;
    float x0f = floorf(ixf), x1f = x0f + 1.0f;
    float y0f = floorf(iyf), y1f = y0f + 1.0f;
    float wx1 = ixf - x0f, wx0 = 1.0f - wx1;
    float wy1 = iyf - y0f, wy0 = 1.0f - wy1;
    float vx0 = (x0f >= 0.0f && x0f <= (float)(W_ - 1)) ? 1.0f : 0.0f;
    float vx1 = (x1f >= 0.0f && x1f <= (float)(W_ - 1)) ? 1.0f : 0.0f;
    float vy0 = (y0f >= 0.0f && y0f <= (float)(H_ - 1)) ? 1.0f : 0.0f;
    float vy1 = (y1f >= 0.0f && y1f <= (float)(H_ - 1)) ? 1.0f : 0.0f;
    float w00 = wy0 * wx0 * vy0 * vx0;
    float w01 = wy0 * wx1 * vy0 * vx1;
    float w10 = wy1 * wx0 * vy1 * vx0;
    float w11 = wy1 * wx1 * vy1 * vx1;
    int xi0 = min(max((int)x0f, 0), W_ - 1);
    int xi1 = min(max((int)x1f, 0), W_ - 1);
    int yi0 = min(max((int)y0f, 0), H_ - 1);
    int yi1 = min(max((int)y1f, 0), H_ - 1);
    int o00 = yi0 * W_ + xi0, o01 = yi0 * W_ + xi1;
    int o10 = yi1 * W_ + xi0, o11 = yi1 * W_ + xi1;

    const float* xb = x + (size_t)b * C_ * H_ * W_;

    float fea[64];
    float M[16];
    #pragma unroll
    for (int j = 0; j < 16; j++) M[j] = 0.0f;

    // Pass 1: gather fea0 per channel, accumulate per-expert partial mids
    #pragma unroll
    for (int c = 0; c < 64; c++) {
        const float* p = xb + c * (H_ * W_);
        float f = w00 * __ldg(p + o00);
        f = fmaf(w01, __ldg(p + o01), f);
        f = fmaf(w10, __ldg(p + o10), f);
        f = fmaf(w11, __ldg(p + o11), f);
        fea[c] = f;
        #pragma unroll
        for (int g = 0; g < 4; g++) {
            float4 a = Wc4[c][g];
            M[g * 4 + 0] = fmaf(a.x, f, M[g * 4 + 0]);
            M[g * 4 + 1] = fmaf(a.y, f, M[g * 4 + 1]);
            M[g * 4 + 2] = fmaf(a.z, f, M[g * 4 + 2]);
            M[g * 4 + 3] = fmaf(a.w, f, M[g * 4 + 3]);
        }
    }

    // mid[r] = sum_e rw[e] * M[e*4+r];  q[e*4+r] = rw[e] * mid[r]
    float q[16];
    #pragma unroll
    for (int r = 0; r < 4; r++) {
        float mid = rw0 * M[r];
        mid = fmaf(rw1, M[4 + r], mid);
        mid = fmaf(rw2, M[8 + r], mid);
        mid = fmaf(rw3, M[12 + r], mid);
        q[0 * 4 + r] = rw0 * mid;
        q[1 * 4 + r] = rw1 * mid;
        q[2 * 4 + r] = rw2 * mid;
        q[3 * 4 + r] = rw3 * mid;
    }

    // Pass 2: out[c] = fea0[c] + sum_j We_s[c][j] * q[j]
    float* op = out + (size_t)b * C_ * OH_ * OW_ + (size_t)oy * OW_ + ox;
    #pragma unroll
    for (int c = 0; c < 64; c++) {
        float acc = fea[c];
        #pragma unroll
        for (int g = 0; g < 4; g++) {
            float4 a = We4[c][g];
            acc = fmaf(a.x, q[g * 4 + 0], acc);
            acc = fmaf(a.y, q[g * 4 + 1], acc);
            acc = fmaf(a.z, q[g * 4 + 2], acc);
            acc = fmaf(a.w, q[g * 4 + 3], acc);
        }
        op[(size_t)c * (OH_ * OW_)] = acc;
    }
}

extern "C" void kernel_launch(void* const* d_in, const int* in_sizes, int n_in,
                              void* d_out, int out_size) {
    const float* x    = (const float*)d_in[0];
    const float* wc   = (const float*)d_in[1];
    const float* we   = (const float*)d_in[2];
    const float* w1   = (const float*)d_in[3];
    const float* b1   = (const float*)d_in[4];
    const float* w2   = (const float*)d_in[5];
    const float* b2   = (const float*)d_in[6];
    const float* rww  = (const float*)d_in[7];
    const float* rwb  = (const float*)d_in[8];
    const float* ofw  = (const float*)d_in[9];
    const float* ofb  = (const float*)d_in[10];
    float* out = (float*)d_out;

    mlp4_kernel<<<1, 256>>>(w1, b1, w2, b2, rww, rwb, ofw, ofb);

    dim3 grid(3 * OH_, B_);   // 1152 x 4
    upsample_kernel<<<grid, 128>>>(x, wc, we, out);
}